// round 15
// baseline (speedup 1.0000x reference)
#include <cuda_runtime.h>
#include <cuda_fp16.h>
#include <cstdint>
#include <cstddef>

// Problem dims: out[4096,256] = einsum('ni,nd,dio->no', x, q, W1) + q @ b1
#define NN   4096
#define DIN  256
#define DOUT 256
#define QD   64

// ---------------- smem layout for gemm kernel ----------------
#define XROW   528                // 256 fp16 + pad (16B-aligned, odd 16B count -> conflict-free ldmatrix)
#define SM_XH  0                  // x tile: 128 x 528 B = 67584
#define SM_Q   67584              // q tile: 128 rows x 132 B (33 f32) = 16896
#define QROW   132
#define SM_W   84480              // W bufs: 4 x 18432 B
#define WROW   144                // 64 fp16 = 128 B + 16 B pad
#define WTILE  18432              // 128 o-rows x 144 B
#define SM_B1  158208             // b1 slice: [32 d][128 cols] f32 = 16384 B
#define SMEM_TOTAL 174592

// ---------------- global scratch (static __device__ — no allocation) ----------------
// W transposed fp16: [d(64)][o(256)][i(256)]
__device__ __align__(16) unsigned short g_wh[64ull * 256 * 256];
// k-split partial for s=1: [n(4096)][o(256)] f32
__device__ __align__(16) float g_part[4096ull * 256];

// ---------------- helpers ----------------
__device__ __forceinline__ void mma16816(float c[4],
                                         uint32_t a0, uint32_t a1, uint32_t a2, uint32_t a3,
                                         uint32_t b0, uint32_t b1) {
    asm volatile(
        "mma.sync.aligned.m16n8k16.row.col.f32.f16.f16.f32 "
        "{%0,%1,%2,%3}, {%4,%5,%6,%7}, {%8,%9}, {%0,%1,%2,%3};"
        : "+f"(c[0]), "+f"(c[1]), "+f"(c[2]), "+f"(c[3])
        : "r"(a0), "r"(a1), "r"(a2), "r"(a3), "r"(b0), "r"(b1));
}

__device__ __forceinline__ void ldsm4(uint32_t r[4], uint32_t addr) {
    asm volatile("ldmatrix.sync.aligned.m8n8.x4.shared.b16 {%0,%1,%2,%3}, [%4];"
                 : "=r"(r[0]), "=r"(r[1]), "=r"(r[2]), "=r"(r[3]) : "r"(addr));
}

__device__ __forceinline__ uint32_t s2u(const void* p) {
    uint32_t a;
    asm("{ .reg .u64 t; cvta.to.shared.u64 t, %1; cvt.u32.u64 %0, t; }" : "=r"(a) : "l"(p));
    return a;
}

__device__ __forceinline__ void cp16(uint32_t dst, const void* src) {
    asm volatile("cp.async.cg.shared.global [%0], [%1], 16;" :: "r"(dst), "l"(src) : "memory");
}
#define CP_COMMIT() asm volatile("cp.async.commit_group;" ::: "memory")
#define CP_WAIT2()  asm volatile("cp.async.wait_group 2;" ::: "memory")

// ---------------- prep: W1[d][i][o] f32 -> g_wh [d][o][i] fp16 (float4 loads) ----------------
__global__ void __launch_bounds__(256) prep_kernel(const float* __restrict__ W1) {
    __shared__ unsigned short sh[64 * 66];   // [i][o], pad 66 breaks transpose conflicts
    int bx = blockIdx.x;                     // 1024 blocks: d(64) x ib(4) x ob(4)
    int d  = bx >> 4;
    int ib = (bx >> 2) & 3;
    int ob = bx & 3;
    int i0 = ib * 64, o0 = ob * 64;
    int tid = threadIdx.x;

    #pragma unroll
    for (int j = 0; j < 4; j++) {
        int e = tid + j * 256;               // 1024 float4 (4096 elements)
        int ii = e >> 4, o4 = e & 15;
        float4 w = *(const float4*)(W1 + ((size_t)d * DIN + (i0 + ii)) * DOUT + o0 + o4 * 4);
        uint32_t p0 = (uint32_t)__half_as_ushort(__float2half_rn(w.x)) |
                      ((uint32_t)__half_as_ushort(__float2half_rn(w.y)) << 16);
        uint32_t p1 = (uint32_t)__half_as_ushort(__float2half_rn(w.z)) |
                      ((uint32_t)__half_as_ushort(__float2half_rn(w.w)) << 16);
        int base = ii * 66 + o4 * 4;         // even -> 4B aligned
        *(uint32_t*)(sh + base)     = p0;
        *(uint32_t*)(sh + base + 2) = p1;
    }
    __syncthreads();

    #pragma unroll
    for (int j = 0; j < 8; j++) {
        int e = tid + j * 256;               // 2048 u32 (pairs of i)
        int o = e >> 5, ip = e & 31;
        uint32_t hv = (uint32_t)sh[(ip * 2) * 66 + o] | ((uint32_t)sh[(ip * 2 + 1) * 66 + o] << 16);
        size_t idx = ((size_t)(d * 256 + o0 + o)) * 128 + (size_t)(ib * 32 + ip);
        ((uint32_t*)g_wh)[idx] = hv;
    }
}

// ---------------- add: out += g_part (pure streaming) ----------------
__global__ void __launch_bounds__(256) add_kernel(float* __restrict__ out) {
    int i = blockIdx.x * 256 + threadIdx.x;  // float4 index, 1024 x 256 = 262144
    float4 a = ((const float4*)out)[i];
    float4 b = ((const float4*)g_part)[i];
    ((float4*)out)[i] = make_float4(a.x + b.x, a.y + b.y, a.z + b.z, a.w + b.w);
}

// ---------------- W chunk loader: 16 KB via cp.async (512 threads) ----------------
__device__ __forceinline__ void load_chunk(uint32_t smu, int buf, int d_glob, int kc,
                                           int n0, int tid) {
    #pragma unroll
    for (int j = 0; j < 2; j++) {
        int e = tid + j * 512;               // 1024 x 16 B
        int o = e >> 3, seg = e & 7;
        const unsigned short* src = g_wh +
            ((size_t)(d_glob * 256 + n0 + o)) * 256 + (size_t)(kc * 64 + seg * 8);
        uint32_t dst = smu + SM_W + (uint32_t)buf * WTILE +
                       (uint32_t)o * WROW + (uint32_t)seg * 16;
        cp16(dst, src);
    }
}

// ---------------- main GEMM: 128 CTAs x 512 threads (16 warps, 32x32 warp tile) ----------------
extern __shared__ unsigned char sm[];

__global__ void __launch_bounds__(512, 1) gemm_kernel(const float* __restrict__ x,
                                                      const float* __restrict__ q,
                                                      const float* __restrict__ b1g,
                                                      float* __restrict__ out) {
    int tid = threadIdx.x;
    int wid = tid >> 5, lane = tid & 31;
    int g = lane >> 2, t = lane & 3;
    int lrow = lane & 7;
    int b3 = (lane >> 3) & 1;                // ldmatrix matrix-index bit 0
    int b4 = (lane >> 4) & 1;                // ldmatrix matrix-index bit 1
    int mwarp = wid & 3;                     // 0..3 (32 rows each)
    int nwarp = wid >> 2;                    // 0..3 (32 cols each)

    int mtile = blockIdx.x >> 2;             // 0..31
    int ntile = (blockIdx.x >> 1) & 1;       // 0..1
    int s     = blockIdx.x & 1;              // k-split over d
    int m0 = mtile * 128;
    int n0 = ntile * 128;
    int d0 = s * 32;

    uint32_t smu = s2u(sm);

    // prefetch chunks 0..2 (overlaps with prolog)
    load_chunk(smu, 0, d0, 0, n0, tid);
    CP_COMMIT();
    load_chunk(smu, 1, d0, 1, n0, tid);
    CP_COMMIT();
    load_chunk(smu, 2, d0, 2, n0, tid);
    CP_COMMIT();

    // ---- prolog: x tile -> fp16 smem; q slice + b1 slice -> smem ----
    #pragma unroll
    for (int j = 0; j < 16; j++) {
        int e = tid + j * 512;               // 8192 float4-groups
        int m = e >> 6, c4 = e & 63;
        float4 v = *(const float4*)(x + (size_t)(m0 + m) * DIN + c4 * 4);
        uint32_t p0 = (uint32_t)__half_as_ushort(__float2half_rn(v.x)) |
                      ((uint32_t)__half_as_ushort(__float2half_rn(v.y)) << 16);
        uint32_t p1 = (uint32_t)__half_as_ushort(__float2half_rn(v.z)) |
                      ((uint32_t)__half_as_ushort(__float2half_rn(v.w)) << 16);
        *(uint2*)(sm + SM_XH + m * XROW + c4 * 8) = make_uint2(p0, p1);
    }
    #pragma unroll
    for (int j = 0; j < 8; j++) {
        int e = tid + j * 512;               // 4096 q values (128 rows x 32 local d)
        int m = e >> 5, dl = e & 31;
        *(float*)(sm + SM_Q + m * QROW + dl * 4) = q[(size_t)(m0 + m) * QD + d0 + dl];
    }
    #pragma unroll
    for (int j = 0; j < 2; j++) {
        int e = tid + j * 512;               // 1024 float4 = b1[d0..d0+31][n0..n0+127]
        int dl = e >> 5, c4 = e & 31;
        float4 v = *(const float4*)(b1g + (size_t)(d0 + dl) * DOUT + n0 + c4 * 4);
        *(float4*)(sm + SM_B1 + (size_t)(dl * 128 + c4 * 4) * 4) = v;
    }

    // per-lane ldmatrix base addresses
    uint32_t aoff[2];
    #pragma unroll
    for (int mt = 0; mt < 2; mt++)
        aoff[mt] = smu + SM_XH +
                   (uint32_t)(mwarp * 32 + mt * 16 + lrow + b3 * 8) * XROW + (uint32_t)b4 * 16;
    uint32_t boff[2];
    #pragma unroll
    for (int p = 0; p < 2; p++)
        boff[p] = smu + SM_W +
                  (uint32_t)(nwarp * 32 + p * 16 + b4 * 8 + lrow) * WROW + (uint32_t)b3 * 16;

    float y[2][4][4];
    float acc[2][4][4];
    #pragma unroll
    for (int mt = 0; mt < 2; mt++)
        #pragma unroll
        for (int nt = 0; nt < 4; nt++)
            #pragma unroll
            for (int k = 0; k < 4; k++) { y[mt][nt][k] = 0.f; acc[mt][nt][k] = 0.f; }

    int buf = 0;
    #pragma unroll 1
    for (int cn = 0; cn < 128; cn++) {
        CP_WAIT2();                          // chunk cn arrived (3 in flight max)
        __syncthreads();                     // visibility + all warps done with buf being reloaded
        int nx = cn + 3;
        if (nx < 128)
            load_chunk(smu, (buf + 3) & 3, d0 + (nx >> 2), nx & 3, n0, tid);
        CP_COMMIT();

        int kc = cn & 3;
        uint32_t wb = (uint32_t)buf * WTILE;
        #pragma unroll
        for (int ks = 0; ks < 4; ks++) {
            uint32_t ak = (uint32_t)(kc * 128 + ks * 32);
            uint32_t a[2][4], b[4][2];
            #pragma unroll
            for (int mt = 0; mt < 2; mt++) ldsm4(a[mt], aoff[mt] + ak);
            {
                uint32_t r[4];
                ldsm4(r, boff[0] + wb + ks * 32);
                b[0][0] = r[0]; b[0][1] = r[1]; b[1][0] = r[2]; b[1][1] = r[3];
                ldsm4(r, boff[1] + wb + ks * 32);
                b[2][0] = r[0]; b[2][1] = r[1]; b[3][0] = r[2]; b[3][1] = r[3];
            }
            #pragma unroll
            for (int mt = 0; mt < 2; mt++)
                #pragma unroll
                for (int nt = 0; nt < 4; nt++)
                    mma16816(y[mt][nt], a[mt][0], a[mt][1], a[mt][2], a[mt][3],
                             b[nt][0], b[nt][1]);
        }
        buf = (buf + 1) & 3;

        if (kc == 3) {
            // ---- fold (Y_d + b1[d]) into acc with q[m, d] ----
            int d = cn >> 2;                 // local d 0..31
            const float* bs = (const float*)(sm + SM_B1 + (size_t)d * 128 * 4);
            #pragma unroll
            for (int mt = 0; mt < 2; mt++) {
                int rbase = mwarp * 32 + mt * 16 + g;
                float q0 = *(const float*)(sm + SM_Q + rbase * QROW + d * 4);
                float q1 = *(const float*)(sm + SM_Q + (rbase + 8) * QROW + d * 4);
                #pragma unroll
                for (int nt = 0; nt < 4; nt++) {
                    float2 bv = *(const float2*)(bs + nwarp * 32 + nt * 8 + t * 2);
                    acc[mt][nt][0] += q0 * (y[mt][nt][0] + bv.x);
                    acc[mt][nt][1] += q0 * (y[mt][nt][1] + bv.y);
                    acc[mt][nt][2] += q1 * (y[mt][nt][2] + bv.x);
                    acc[mt][nt][3] += q1 * (y[mt][nt][3] + bv.y);
                    y[mt][nt][0] = 0.f; y[mt][nt][1] = 0.f;
                    y[mt][nt][2] = 0.f; y[mt][nt][3] = 0.f;
                }
            }
        }
    }

    // ---- write: s=0 -> out, s=1 -> g_part ----
    float* pp = (s == 0) ? out : g_part;
    #pragma unroll
    for (int mt = 0; mt < 2; mt++) {
        int r0 = m0 + mwarp * 32 + mt * 16 + g;
        #pragma unroll
        for (int nt = 0; nt < 4; nt++) {
            int col = n0 + nwarp * 32 + nt * 8 + t * 2;
            *(float2*)(pp + (size_t)r0 * DOUT + col)       = make_float2(acc[mt][nt][0], acc[mt][nt][1]);
            *(float2*)(pp + (size_t)(r0 + 8) * DOUT + col) = make_float2(acc[mt][nt][2], acc[mt][nt][3]);
        }
    }
}

// ---------------- launch ----------------
extern "C" void kernel_launch(void* const* d_in, const int* in_sizes, int n_in,
                              void* d_out, int out_size) {
    const float* x  = (const float*)d_in[0];
    const float* q  = (const float*)d_in[1];
    const float* W1 = (const float*)d_in[2];
    const float* b1 = (const float*)d_in[3];
    float* out = (float*)d_out;

    cudaFuncSetAttribute(gemm_kernel, cudaFuncAttributeMaxDynamicSharedMemorySize, SMEM_TOTAL);

    prep_kernel<<<1024, 256>>>(W1);
    gemm_kernel<<<128, 512, SMEM_TOTAL>>>(x, q, b1, out);
    add_kernel<<<1024, 256>>>(out);
}

// round 16
// speedup vs baseline: 1.0560x; 1.0560x over previous
#include <cuda_runtime.h>
#include <cuda_fp16.h>
#include <cstdint>
#include <cstddef>

// Problem dims: out[4096,256] = einsum('ni,nd,dio->no', x, q, W1) + q @ b1
#define NN   4096
#define DIN  256
#define DOUT 256
#define QD   64

// ---------------- smem layout for gemm kernel ----------------
#define XROW   528                // 256 fp16 + pad (conflict-free ldmatrix)
#define SM_XH  0                  // x tile: 128 x 528 B = 67584
#define SM_Q   67584              // q tile f32: 128 rows x 132 B = 16896
#define QROW   132
#define SM_W   84480              // W bufs: 4 x 18432 B = 73728
#define WROW   144                // 64 fp16 = 128 B + 16 B pad
#define WTILE  18432              // 128 o-rows x 144 B
#define SM_QH  158208             // q fp16 tile: 128 x 80 B = 10240 (32 d + pad)
#define QHROW  80
#define SM_B1T 168448             // b1^T fp16 tile: 128 o x 80 B = 10240 (32 d + pad)
#define SMEM_TOTAL 178688

// ---------------- global scratch (static __device__ — no allocation) ----------------
// W transposed fp16: [d(64)][o(256)][i(256)]
__device__ __align__(16) unsigned short g_wh[64ull * 256 * 256];

// ---------------- helpers ----------------
__device__ __forceinline__ void mma16816(float c[4],
                                         uint32_t a0, uint32_t a1, uint32_t a2, uint32_t a3,
                                         uint32_t b0, uint32_t b1) {
    asm volatile(
        "mma.sync.aligned.m16n8k16.row.col.f32.f16.f16.f32 "
        "{%0,%1,%2,%3}, {%4,%5,%6,%7}, {%8,%9}, {%0,%1,%2,%3};"
        : "+f"(c[0]), "+f"(c[1]), "+f"(c[2]), "+f"(c[3])
        : "r"(a0), "r"(a1), "r"(a2), "r"(a3), "r"(b0), "r"(b1));
}

__device__ __forceinline__ void ldsm4(uint32_t r[4], uint32_t addr) {
    asm volatile("ldmatrix.sync.aligned.m8n8.x4.shared.b16 {%0,%1,%2,%3}, [%4];"
                 : "=r"(r[0]), "=r"(r[1]), "=r"(r[2]), "=r"(r[3]) : "r"(addr));
}

__device__ __forceinline__ uint32_t s2u(const void* p) {
    uint32_t a;
    asm("{ .reg .u64 t; cvta.to.shared.u64 t, %1; cvt.u32.u64 %0, t; }" : "=r"(a) : "l"(p));
    return a;
}

__device__ __forceinline__ void cp16(uint32_t dst, const void* src) {
    asm volatile("cp.async.cg.shared.global [%0], [%1], 16;" :: "r"(dst), "l"(src) : "memory");
}
#define CP_COMMIT() asm volatile("cp.async.commit_group;" ::: "memory")
#define CP_WAIT2()  asm volatile("cp.async.wait_group 2;" ::: "memory")

// ---------------- prep: zero out + W1[d][i][o] f32 -> g_wh [d][o][i] fp16 ----------------
__global__ void __launch_bounds__(256) prep_kernel(const float* __restrict__ W1,
                                                   float* __restrict__ out) {
    __shared__ unsigned short sh[64 * 66];   // [i][o], pad 66 breaks transpose conflicts
    int bx = blockIdx.x;                     // 1024 blocks: d(64) x ib(4) x ob(4)
    int tid = threadIdx.x;

    // zero the output (1024*256 float4 == 4096*256 floats exactly)
    ((float4*)out)[bx * 256 + tid] = make_float4(0.f, 0.f, 0.f, 0.f);

    int d  = bx >> 4;
    int ib = (bx >> 2) & 3;
    int ob = bx & 3;
    int i0 = ib * 64, o0 = ob * 64;

    #pragma unroll
    for (int j = 0; j < 4; j++) {
        int e = tid + j * 256;               // 1024 float4 (4096 elements)
        int ii = e >> 4, o4 = e & 15;
        float4 w = *(const float4*)(W1 + ((size_t)d * DIN + (i0 + ii)) * DOUT + o0 + o4 * 4);
        uint32_t p0 = (uint32_t)__half_as_ushort(__float2half_rn(w.x)) |
                      ((uint32_t)__half_as_ushort(__float2half_rn(w.y)) << 16);
        uint32_t p1 = (uint32_t)__half_as_ushort(__float2half_rn(w.z)) |
                      ((uint32_t)__half_as_ushort(__float2half_rn(w.w)) << 16);
        int base = ii * 66 + o4 * 4;         // even -> 4B aligned
        *(uint32_t*)(sh + base)     = p0;
        *(uint32_t*)(sh + base + 2) = p1;
    }
    __syncthreads();

    #pragma unroll
    for (int j = 0; j < 8; j++) {
        int e = tid + j * 256;               // 2048 u32 (pairs of i)
        int o = e >> 5, ip = e & 31;
        uint32_t hv = (uint32_t)sh[(ip * 2) * 66 + o] | ((uint32_t)sh[(ip * 2 + 1) * 66 + o] << 16);
        size_t idx = ((size_t)(d * 256 + o0 + o)) * 128 + (size_t)(ib * 32 + ip);
        ((uint32_t*)g_wh)[idx] = hv;
    }
}

// ---------------- W chunk loader: 16 KB via cp.async (512 threads) ----------------
__device__ __forceinline__ void load_chunk(uint32_t smu, int buf, int d_glob, int kc,
                                           int n0, int tid) {
    #pragma unroll
    for (int j = 0; j < 2; j++) {
        int e = tid + j * 512;               // 1024 x 16 B
        int o = e >> 3, seg = e & 7;
        const unsigned short* src = g_wh +
            ((size_t)(d_glob * 256 + n0 + o)) * 256 + (size_t)(kc * 64 + seg * 8);
        uint32_t dst = smu + SM_W + (uint32_t)buf * WTILE +
                       (uint32_t)o * WROW + (uint32_t)seg * 16;
        cp16(dst, src);
    }
}

// ---------------- main GEMM: 128 CTAs x 512 threads (16 warps, 32x32 warp tile) ----------------
extern __shared__ unsigned char sm[];

__global__ void __launch_bounds__(512, 1) gemm_kernel(const float* __restrict__ x,
                                                      const float* __restrict__ q,
                                                      const float* __restrict__ b1g,
                                                      float* __restrict__ out) {
    int tid = threadIdx.x;
    int wid = tid >> 5, lane = tid & 31;
    int g = lane >> 2, t = lane & 3;
    int lrow = lane & 7;
    int b3 = (lane >> 3) & 1;                // ldmatrix matrix-index bit 0
    int b4 = (lane >> 4) & 1;                // ldmatrix matrix-index bit 1
    int mwarp = wid & 3;                     // 0..3 (32 rows each)
    int nwarp = wid >> 2;                    // 0..3 (32 cols each)

    int mtile = blockIdx.x >> 2;             // 0..31
    int ntile = (blockIdx.x >> 1) & 1;       // 0..1
    int s     = blockIdx.x & 1;              // k-split over d
    int m0 = mtile * 128;
    int n0 = ntile * 128;
    int d0 = s * 32;

    uint32_t smu = s2u(sm);

    // prefetch chunks 0..2 (overlaps with prolog)
    load_chunk(smu, 0, d0, 0, n0, tid);
    CP_COMMIT();
    load_chunk(smu, 1, d0, 1, n0, tid);
    CP_COMMIT();
    load_chunk(smu, 2, d0, 2, n0, tid);
    CP_COMMIT();

    // ---- prolog: x tile -> fp16 smem; q slice (f32 + fp16); b1^T slice (fp16) ----
    #pragma unroll
    for (int j = 0; j < 16; j++) {
        int e = tid + j * 512;               // 8192 float4-groups
        int m = e >> 6, c4 = e & 63;
        float4 v = *(const float4*)(x + (size_t)(m0 + m) * DIN + c4 * 4);
        uint32_t p0 = (uint32_t)__half_as_ushort(__float2half_rn(v.x)) |
                      ((uint32_t)__half_as_ushort(__float2half_rn(v.y)) << 16);
        uint32_t p1 = (uint32_t)__half_as_ushort(__float2half_rn(v.z)) |
                      ((uint32_t)__half_as_ushort(__float2half_rn(v.w)) << 16);
        *(uint2*)(sm + SM_XH + m * XROW + c4 * 8) = make_uint2(p0, p1);
    }
    #pragma unroll
    for (int j = 0; j < 8; j++) {
        int e = tid + j * 512;               // 4096 q values (128 rows x 32 local d)
        int m = e >> 5, dl = e & 31;
        float qv = q[(size_t)(m0 + m) * QD + d0 + dl];
        *(float*)(sm + SM_Q + m * QROW + dl * 4) = qv;
        *(unsigned short*)(sm + SM_QH + m * QHROW + dl * 2) =
            __half_as_ushort(__float2half_rn(qv));
    }
    #pragma unroll
    for (int j = 0; j < 8; j++) {
        int e = tid + j * 512;               // 4096: b1[d0+dl][n0+o] -> b1t[o][dl]
        int dl = e >> 7, o = e & 127;
        float bv = b1g[(size_t)(d0 + dl) * DOUT + n0 + o];
        *(unsigned short*)(sm + SM_B1T + o * QHROW + dl * 2) =
            __half_as_ushort(__float2half_rn(bv));
    }

    // per-lane ldmatrix base addresses
    uint32_t aoff[2];
    #pragma unroll
    for (int mt = 0; mt < 2; mt++)
        aoff[mt] = smu + SM_XH +
                   (uint32_t)(mwarp * 32 + mt * 16 + lrow + b3 * 8) * XROW + (uint32_t)b4 * 16;
    uint32_t boff[2];
    #pragma unroll
    for (int p = 0; p < 2; p++)
        boff[p] = smu + SM_W +
                  (uint32_t)(nwarp * 32 + p * 16 + b4 * 8 + lrow) * WROW + (uint32_t)b3 * 16;
    uint32_t qhoff[2];
    #pragma unroll
    for (int mt = 0; mt < 2; mt++)
        qhoff[mt] = smu + SM_QH +
                    (uint32_t)(mwarp * 32 + mt * 16 + lrow + b3 * 8) * QHROW + (uint32_t)b4 * 16;
    uint32_t btoff[2];
    #pragma unroll
    for (int p = 0; p < 2; p++)
        btoff[p] = smu + SM_B1T +
                   (uint32_t)(nwarp * 32 + p * 16 + b4 * 8 + lrow) * QHROW + (uint32_t)b3 * 16;

    float y[2][4][4];
    float acc[2][4][4];
    #pragma unroll
    for (int mt = 0; mt < 2; mt++)
        #pragma unroll
        for (int nt = 0; nt < 4; nt++)
            #pragma unroll
            for (int k = 0; k < 4; k++) { y[mt][nt][k] = 0.f; acc[mt][nt][k] = 0.f; }

    // ---- bias MMA: acc += q_slice(fp16) @ b1t_slice(fp16)  (2 k-steps, 16 HMMA) ----
    __syncthreads();
    #pragma unroll
    for (int ks = 0; ks < 2; ks++) {
        uint32_t a[2][4], b[4][2];
        #pragma unroll
        for (int mt = 0; mt < 2; mt++) ldsm4(a[mt], qhoff[mt] + ks * 32);
        {
            uint32_t r[4];
            ldsm4(r, btoff[0] + ks * 32);
            b[0][0] = r[0]; b[0][1] = r[1]; b[1][0] = r[2]; b[1][1] = r[3];
            ldsm4(r, btoff[1] + ks * 32);
            b[2][0] = r[0]; b[2][1] = r[1]; b[3][0] = r[2]; b[3][1] = r[3];
        }
        #pragma unroll
        for (int mt = 0; mt < 2; mt++)
            #pragma unroll
            for (int nt = 0; nt < 4; nt++)
                mma16816(acc[mt][nt], a[mt][0], a[mt][1], a[mt][2], a[mt][3],
                         b[nt][0], b[nt][1]);
    }

    int buf = 0;
    #pragma unroll 1
    for (int cn = 0; cn < 128; cn++) {
        CP_WAIT2();                          // chunk cn arrived (3 in flight max)
        __syncthreads();                     // visibility + all warps done with buf being reloaded
        int nx = cn + 3;
        if (nx < 128)
            load_chunk(smu, (buf + 3) & 3, d0 + (nx >> 2), nx & 3, n0, tid);
        CP_COMMIT();

        int kc = cn & 3;
        uint32_t wb = (uint32_t)buf * WTILE;
        #pragma unroll
        for (int ks = 0; ks < 4; ks++) {
            uint32_t ak = (uint32_t)(kc * 128 + ks * 32);
            uint32_t a[2][4], b[4][2];
            #pragma unroll
            for (int mt = 0; mt < 2; mt++) ldsm4(a[mt], aoff[mt] + ak);
            {
                uint32_t r[4];
                ldsm4(r, boff[0] + wb + ks * 32);
                b[0][0] = r[0]; b[0][1] = r[1]; b[1][0] = r[2]; b[1][1] = r[3];
                ldsm4(r, boff[1] + wb + ks * 32);
                b[2][0] = r[0]; b[2][1] = r[1]; b[3][0] = r[2]; b[3][1] = r[3];
            }
            #pragma unroll
            for (int mt = 0; mt < 2; mt++)
                #pragma unroll
                for (int nt = 0; nt < 4; nt++)
                    mma16816(y[mt][nt], a[mt][0], a[mt][1], a[mt][2], a[mt][3],
                             b[nt][0], b[nt][1]);
        }
        buf = (buf + 1) & 3;

        if (kc == 3) {
            // ---- fold Y_d into acc with q[m, d] ----
            int d = cn >> 2;
            #pragma unroll
            for (int mt = 0; mt < 2; mt++) {
                int rbase = mwarp * 32 + mt * 16 + g;
                float q0 = *(const float*)(sm + SM_Q + rbase * QROW + d * 4);
                float q1 = *(const float*)(sm + SM_Q + (rbase + 8) * QROW + d * 4);
                #pragma unroll
                for (int nt = 0; nt < 4; nt++) {
                    acc[mt][nt][0] += q0 * y[mt][nt][0];
                    acc[mt][nt][1] += q0 * y[mt][nt][1];
                    acc[mt][nt][2] += q1 * y[mt][nt][2];
                    acc[mt][nt][3] += q1 * y[mt][nt][3];
                    y[mt][nt][0] = 0.f; y[mt][nt][1] = 0.f;
                    y[mt][nt][2] = 0.f; y[mt][nt][3] = 0.f;
                }
            }
        }
    }

    // ---- merge both k-splits: atomicAdd into zeroed out (2-operand add = commutative) ----
    #pragma unroll
    for (int mt = 0; mt < 2; mt++) {
        int r0 = m0 + mwarp * 32 + mt * 16 + g;
        #pragma unroll
        for (int nt = 0; nt < 4; nt++) {
            int col = n0 + nwarp * 32 + nt * 8 + t * 2;
            float* p0 = out + (size_t)r0 * DOUT + col;
            float* p1 = out + (size_t)(r0 + 8) * DOUT + col;
            atomicAdd(p0,     acc[mt][nt][0]);
            atomicAdd(p0 + 1, acc[mt][nt][1]);
            atomicAdd(p1,     acc[mt][nt][2]);
            atomicAdd(p1 + 1, acc[mt][nt][3]);
        }
    }
}

// ---------------- launch ----------------
extern "C" void kernel_launch(void* const* d_in, const int* in_sizes, int n_in,
                              void* d_out, int out_size) {
    const float* x  = (const float*)d_in[0];
    const float* q  = (const float*)d_in[1];
    const float* W1 = (const float*)d_in[2];
    const float* b1 = (const float*)d_in[3];
    float* out = (float*)d_out;

    cudaFuncSetAttribute(gemm_kernel, cudaFuncAttributeMaxDynamicSharedMemorySize, SMEM_TOTAL);

    prep_kernel<<<1024, 256>>>(W1, out);
    gemm_kernel<<<128, 512, SMEM_TOTAL>>>(x, q, b1, out);
}

// round 17
// speedup vs baseline: 1.1357x; 1.0755x over previous
#include <cuda_runtime.h>
#include <cuda_fp16.h>
#include <cstdint>
#include <cstddef>

// Problem dims: out[4096,256] = einsum('ni,nd,dio->no', x, q, W1) + q @ b1
#define NN   4096
#define DIN  256
#define DOUT 256
#define QD   64

// ---------------- smem layout for gemm kernel ----------------
#define XROW   528                // 256 fp16 + pad (conflict-free ldmatrix)
#define SM_XH  0                  // x tile: 128 x 528 B = 67584
#define SM_Q   67584              // q tile f32: 128 rows x 132 B = 16896
#define QROW   132
#define SM_W   84480              // W bufs: 3 x 34816 B = 104448
#define WROW   272                // 128 fp16 = 256 B + 16 B pad (odd x16 -> conflict-free)
#define WTILE  34816              // 128 o-rows x 272 B
#define SM_QH  188928             // q fp16 tile: 128 x 80 B = 10240 (32 d + pad)
#define QHROW  80
#define SM_B1T 199168             // b1^T fp16 tile: 128 o x 80 B = 10240
#define SMEM_TOTAL 209408

// ---------------- global scratch (static __device__ — no allocation) ----------------
// W transposed fp16: [d(64)][o(256)][i(256)]
__device__ __align__(16) unsigned short g_wh[64ull * 256 * 256];

// ---------------- helpers ----------------
__device__ __forceinline__ void mma16816(float c[4],
                                         uint32_t a0, uint32_t a1, uint32_t a2, uint32_t a3,
                                         uint32_t b0, uint32_t b1) {
    asm volatile(
        "mma.sync.aligned.m16n8k16.row.col.f32.f16.f16.f32 "
        "{%0,%1,%2,%3}, {%4,%5,%6,%7}, {%8,%9}, {%0,%1,%2,%3};"
        : "+f"(c[0]), "+f"(c[1]), "+f"(c[2]), "+f"(c[3])
        : "r"(a0), "r"(a1), "r"(a2), "r"(a3), "r"(b0), "r"(b1));
}

__device__ __forceinline__ void ldsm4(uint32_t r[4], uint32_t addr) {
    asm volatile("ldmatrix.sync.aligned.m8n8.x4.shared.b16 {%0,%1,%2,%3}, [%4];"
                 : "=r"(r[0]), "=r"(r[1]), "=r"(r[2]), "=r"(r[3]) : "r"(addr));
}

__device__ __forceinline__ uint32_t s2u(const void* p) {
    uint32_t a;
    asm("{ .reg .u64 t; cvta.to.shared.u64 t, %1; cvt.u32.u64 %0, t; }" : "=r"(a) : "l"(p));
    return a;
}

__device__ __forceinline__ void cp16(uint32_t dst, const void* src) {
    asm volatile("cp.async.cg.shared.global [%0], [%1], 16;" :: "r"(dst), "l"(src) : "memory");
}
#define CP_COMMIT() asm volatile("cp.async.commit_group;" ::: "memory")
#define CP_WAIT1()  asm volatile("cp.async.wait_group 1;" ::: "memory")

// ---------------- prep: zero out + W1[d][i][o] f32 -> g_wh [d][o][i] fp16 ----------------
__global__ void __launch_bounds__(256) prep_kernel(const float* __restrict__ W1,
                                                   float* __restrict__ out) {
    __shared__ unsigned short sh[64 * 66];   // [i][o], pad 66 breaks transpose conflicts
    int bx = blockIdx.x;                     // 1024 blocks: d(64) x ib(4) x ob(4)
    int tid = threadIdx.x;

    // zero the output (1024*256 float4 == 4096*256 floats exactly)
    ((float4*)out)[bx * 256 + tid] = make_float4(0.f, 0.f, 0.f, 0.f);

    int d  = bx >> 4;
    int ib = (bx >> 2) & 3;
    int ob = bx & 3;
    int i0 = ib * 64, o0 = ob * 64;

    #pragma unroll
    for (int j = 0; j < 4; j++) {
        int e = tid + j * 256;               // 1024 float4 (4096 elements)
        int ii = e >> 4, o4 = e & 15;
        float4 w = *(const float4*)(W1 + ((size_t)d * DIN + (i0 + ii)) * DOUT + o0 + o4 * 4);
        uint32_t p0 = (uint32_t)__half_as_ushort(__float2half_rn(w.x)) |
                      ((uint32_t)__half_as_ushort(__float2half_rn(w.y)) << 16);
        uint32_t p1 = (uint32_t)__half_as_ushort(__float2half_rn(w.z)) |
                      ((uint32_t)__half_as_ushort(__float2half_rn(w.w)) << 16);
        int base = ii * 66 + o4 * 4;         // even -> 4B aligned
        *(uint32_t*)(sh + base)     = p0;
        *(uint32_t*)(sh + base + 2) = p1;
    }
    __syncthreads();

    #pragma unroll
    for (int j = 0; j < 8; j++) {
        int e = tid + j * 256;               // 2048 u32 (pairs of i)
        int o = e >> 5, ip = e & 31;
        uint32_t hv = (uint32_t)sh[(ip * 2) * 66 + o] | ((uint32_t)sh[(ip * 2 + 1) * 66 + o] << 16);
        size_t idx = ((size_t)(d * 256 + o0 + o)) * 128 + (size_t)(ib * 32 + ip);
        ((uint32_t*)g_wh)[idx] = hv;
    }
}

// ---------------- W chunk loader: 32 KB (128 o x 128 i) via cp.async (512 threads) ----------------
__device__ __forceinline__ void load_chunk(uint32_t smu, int buf, int d_glob, int ih,
                                           int n0, int tid) {
    #pragma unroll
    for (int j = 0; j < 4; j++) {
        int e = tid + j * 512;               // 2048 x 16 B
        int o = e >> 4, seg = e & 15;
        const unsigned short* src = g_wh +
            ((size_t)(d_glob * 256 + n0 + o)) * 256 + (size_t)(ih * 128 + seg * 8);
        uint32_t dst = smu + SM_W + (uint32_t)buf * WTILE +
                       (uint32_t)o * WROW + (uint32_t)seg * 16;
        cp16(dst, src);
    }
}

// ---------------- main GEMM: 128 CTAs x 512 threads (16 warps, 32x32 warp tile) ----------------
extern __shared__ unsigned char sm[];

__global__ void __launch_bounds__(512, 1) gemm_kernel(const float* __restrict__ x,
                                                      const float* __restrict__ q,
                                                      const float* __restrict__ b1g,
                                                      float* __restrict__ out) {
    int tid = threadIdx.x;
    int wid = tid >> 5, lane = tid & 31;
    int g = lane >> 2, t = lane & 3;
    int lrow = lane & 7;
    int b3 = (lane >> 3) & 1;                // ldmatrix matrix-index bit 0
    int b4 = (lane >> 4) & 1;                // ldmatrix matrix-index bit 1
    int mwarp = wid & 3;                     // 0..3 (32 rows each)
    int nwarp = wid >> 2;                    // 0..3 (32 cols each)

    int mtile = blockIdx.x >> 2;             // 0..31
    int ntile = (blockIdx.x >> 1) & 1;       // 0..1
    int s     = blockIdx.x & 1;              // k-split over d
    int m0 = mtile * 128;
    int n0 = ntile * 128;
    int d0 = s * 32;

    uint32_t smu = s2u(sm);

    // prefetch chunks 0..1 (overlaps with prolog); 3 bufs, 1 load in flight steady-state
    load_chunk(smu, 0, d0, 0, n0, tid);
    CP_COMMIT();
    load_chunk(smu, 1, d0, 1, n0, tid);
    CP_COMMIT();

    // ---- prolog: x tile -> fp16 smem; q slice (f32 + fp16); b1^T slice (fp16) ----
    #pragma unroll
    for (int j = 0; j < 16; j++) {
        int e = tid + j * 512;               // 8192 float4-groups
        int m = e >> 6, c4 = e & 63;
        float4 v = *(const float4*)(x + (size_t)(m0 + m) * DIN + c4 * 4);
        uint32_t p0 = (uint32_t)__half_as_ushort(__float2half_rn(v.x)) |
                      ((uint32_t)__half_as_ushort(__float2half_rn(v.y)) << 16);
        uint32_t p1 = (uint32_t)__half_as_ushort(__float2half_rn(v.z)) |
                      ((uint32_t)__half_as_ushort(__float2half_rn(v.w)) << 16);
        *(uint2*)(sm + SM_XH + m * XROW + c4 * 8) = make_uint2(p0, p1);
    }
    #pragma unroll
    for (int j = 0; j < 8; j++) {
        int e = tid + j * 512;               // 4096 q values (128 rows x 32 local d)
        int m = e >> 5, dl = e & 31;
        float qv = q[(size_t)(m0 + m) * QD + d0 + dl];
        *(float*)(sm + SM_Q + m * QROW + dl * 4) = qv;
        *(unsigned short*)(sm + SM_QH + m * QHROW + dl * 2) =
            __half_as_ushort(__float2half_rn(qv));
    }
    #pragma unroll
    for (int j = 0; j < 8; j++) {
        int e = tid + j * 512;               // 4096: b1[d0+dl][n0+o] -> b1t[o][dl]
        int dl = e >> 7, o = e & 127;
        float bv = b1g[(size_t)(d0 + dl) * DOUT + n0 + o];
        *(unsigned short*)(sm + SM_B1T + o * QHROW + dl * 2) =
            __half_as_ushort(__float2half_rn(bv));
    }

    // per-lane ldmatrix base addresses
    uint32_t aoff[2];
    #pragma unroll
    for (int mt = 0; mt < 2; mt++)
        aoff[mt] = smu + SM_XH +
                   (uint32_t)(mwarp * 32 + mt * 16 + lrow + b3 * 8) * XROW + (uint32_t)b4 * 16;
    uint32_t boff[2];
    #pragma unroll
    for (int p = 0; p < 2; p++)
        boff[p] = smu + SM_W +
                  (uint32_t)(nwarp * 32 + p * 16 + b4 * 8 + lrow) * WROW + (uint32_t)b3 * 16;
    uint32_t qhoff[2];
    #pragma unroll
    for (int mt = 0; mt < 2; mt++)
        qhoff[mt] = smu + SM_QH +
                    (uint32_t)(mwarp * 32 + mt * 16 + lrow + b3 * 8) * QHROW + (uint32_t)b4 * 16;
    uint32_t btoff[2];
    #pragma unroll
    for (int p = 0; p < 2; p++)
        btoff[p] = smu + SM_B1T +
                   (uint32_t)(nwarp * 32 + p * 16 + b4 * 8 + lrow) * QHROW + (uint32_t)b3 * 16;

    float y[2][4][4];
    float acc[2][4][4];
    #pragma unroll
    for (int mt = 0; mt < 2; mt++)
        #pragma unroll
        for (int nt = 0; nt < 4; nt++)
            #pragma unroll
            for (int k = 0; k < 4; k++) { y[mt][nt][k] = 0.f; acc[mt][nt][k] = 0.f; }

    // ---- bias MMA: acc += q_slice(fp16) @ b1t_slice(fp16)  (2 k-steps, 16 HMMA) ----
    __syncthreads();
    #pragma unroll
    for (int ks = 0; ks < 2; ks++) {
        uint32_t a[2][4], b[4][2];
        #pragma unroll
        for (int mt = 0; mt < 2; mt++) ldsm4(a[mt], qhoff[mt] + ks * 32);
        {
            uint32_t r[4];
            ldsm4(r, btoff[0] + ks * 32);
            b[0][0] = r[0]; b[0][1] = r[1]; b[1][0] = r[2]; b[1][1] = r[3];
            ldsm4(r, btoff[1] + ks * 32);
            b[2][0] = r[0]; b[2][1] = r[1]; b[3][0] = r[2]; b[3][1] = r[3];
        }
        #pragma unroll
        for (int mt = 0; mt < 2; mt++)
            #pragma unroll
            for (int nt = 0; nt < 4; nt++)
                mma16816(acc[mt][nt], a[mt][0], a[mt][1], a[mt][2], a[mt][3],
                         b[nt][0], b[nt][1]);
    }

    int buf = 0;
    #pragma unroll 1
    for (int cn = 0; cn < 64; cn++) {        // chunk = [128 o][128 i] of d=(cn>>1), ih=(cn&1)
        CP_WAIT1();                          // chunk cn arrived (1 load pending allowed)
        __syncthreads();                     // visibility + all warps done with buf being reloaded
        int nx = cn + 2;
        if (nx < 64)
            load_chunk(smu, (buf + 2) % 3, d0 + (nx >> 1), nx & 1, n0, tid);
        CP_COMMIT();

        int ih = cn & 1;
        uint32_t wb = (uint32_t)buf * WTILE;
        #pragma unroll
        for (int ks = 0; ks < 8; ks++) {
            uint32_t ak = (uint32_t)(ih * 256 + ks * 32);
            uint32_t a[2][4], b[4][2];
            #pragma unroll
            for (int mt = 0; mt < 2; mt++) ldsm4(a[mt], aoff[mt] + ak);
            {
                uint32_t r[4];
                ldsm4(r, boff[0] + wb + ks * 32);
                b[0][0] = r[0]; b[0][1] = r[1]; b[1][0] = r[2]; b[1][1] = r[3];
                ldsm4(r, boff[1] + wb + ks * 32);
                b[2][0] = r[0]; b[2][1] = r[1]; b[3][0] = r[2]; b[3][1] = r[3];
            }
            #pragma unroll
            for (int mt = 0; mt < 2; mt++)
                #pragma unroll
                for (int nt = 0; nt < 4; nt++)
                    mma16816(y[mt][nt], a[mt][0], a[mt][1], a[mt][2], a[mt][3],
                             b[nt][0], b[nt][1]);
        }
        buf = (buf + 1) % 3;

        if (ih == 1) {
            // ---- fold Y_d into acc with q[m, d] ----
            int d = cn >> 1;
            #pragma unroll
            for (int mt = 0; mt < 2; mt++) {
                int rbase = mwarp * 32 + mt * 16 + g;
                float q0 = *(const float*)(sm + SM_Q + rbase * QROW + d * 4);
                float q1 = *(const float*)(sm + SM_Q + (rbase + 8) * QROW + d * 4);
                #pragma unroll
                for (int nt = 0; nt < 4; nt++) {
                    acc[mt][nt][0] += q0 * y[mt][nt][0];
                    acc[mt][nt][1] += q0 * y[mt][nt][1];
                    acc[mt][nt][2] += q1 * y[mt][nt][2];
                    acc[mt][nt][3] += q1 * y[mt][nt][3];
                    y[mt][nt][0] = 0.f; y[mt][nt][1] = 0.f;
                    y[mt][nt][2] = 0.f; y[mt][nt][3] = 0.f;
                }
            }
        }
    }

    // ---- merge both k-splits: atomicAdd into zeroed out (2-operand add = commutative) ----
    #pragma unroll
    for (int mt = 0; mt < 2; mt++) {
        int r0 = m0 + mwarp * 32 + mt * 16 + g;
        #pragma unroll
        for (int nt = 0; nt < 4; nt++) {
            int col = n0 + nwarp * 32 + nt * 8 + t * 2;
            float* p0 = out + (size_t)r0 * DOUT + col;
            float* p1 = out + (size_t)(r0 + 8) * DOUT + col;
            atomicAdd(p0,     acc[mt][nt][0]);
            atomicAdd(p0 + 1, acc[mt][nt][1]);
            atomicAdd(p1,     acc[mt][nt][2]);
            atomicAdd(p1 + 1, acc[mt][nt][3]);
        }
    }
}

// ---------------- launch ----------------
extern "C" void kernel_launch(void* const* d_in, const int* in_sizes, int n_in,
                              void* d_out, int out_size) {
    const float* x  = (const float*)d_in[0];
    const float* q  = (const float*)d_in[1];
    const float* W1 = (const float*)d_in[2];
    const float* b1 = (const float*)d_in[3];
    float* out = (float*)d_out;

    cudaFuncSetAttribute(gemm_kernel, cudaFuncAttributeMaxDynamicSharedMemorySize, SMEM_TOTAL);

    prep_kernel<<<1024, 256>>>(W1, out);
    gemm_kernel<<<128, 512, SMEM_TOTAL>>>(x, q, b1, out);
}